// round 1
// baseline (speedup 1.0000x reference)
#include <cuda_runtime.h>

#define HEIGHT  260
#define WIDTH   346
#define H_S     65
#define W_S     86
#define T_STEPS 64
#define BATCH   16
#define IMG     (H_S * W_S)      // 5590

// scratch: exc for all (t,b) — 64*16*5590 floats = 22.9 MB
__device__ float g_exc[T_STEPS * BATCH * IMG];

// ---------------------------------------------------------------------------
// Kernel A: 4x4 avg pool (2 channels) + 2-ch 3x3 conv + ReLU, per (t,b) image
// ---------------------------------------------------------------------------
__global__ void k_exc(const float* __restrict__ x, const float* __restrict__ exc_w) {
    const int tb = blockIdx.x;                       // t*BATCH + b
    const float* xb = x + (long long)tb * 2 * HEIGHT * WIDTH;

    __shared__ float p[2][H_S + 2][W_S + 2];         // pooled, zero-padded halo 1
    __shared__ float w[18];

    const int tid = threadIdx.x;
    if (tid < 18) w[tid] = exc_w[tid];

    float* ps = &p[0][0][0];
    for (int i = tid; i < 2 * (H_S + 2) * (W_S + 2); i += blockDim.x) ps[i] = 0.f;
    __syncthreads();

    // pooling: each task = one (c,i,j) pooled value, 16 loads
    for (int n = tid; n < 2 * IMG; n += blockDim.x) {
        int c   = n / IMG;
        int rem = n - c * IMG;
        int i   = rem / W_S;
        int j   = rem - i * W_S;
        const float* src = xb + ((long long)c * HEIGHT + i * 4) * WIDTH + j * 4;
        float s = 0.f;
        #pragma unroll
        for (int r = 0; r < 4; r++) {
            #pragma unroll
            for (int q = 0; q < 4; q++) s += src[r * WIDTH + q];
        }
        p[c][i + 1][j + 1] = s * (1.f / 16.f);
    }
    __syncthreads();

    // 3x3 conv over 2 channels + relu
    float* out = g_exc + (long long)tb * IMG;
    for (int n = tid; n < IMG; n += blockDim.x) {
        int i = n / W_S;
        int j = n - i * W_S;
        float acc = 0.f;
        #pragma unroll
        for (int c = 0; c < 2; c++)
            #pragma unroll
            for (int ky = 0; ky < 3; ky++)
                #pragma unroll
                for (int kx = 0; kx < 3; kx++)
                    acc += p[c][i + ky][j + kx] * w[c * 9 + ky * 3 + kx];
        out[n] = fmaxf(acc, 0.f);
    }
}

// ---------------------------------------------------------------------------
// Kernel B: recurrent LGMD dynamics. Block = (batch b, row strip s).
// Each thread owns up to 4 pixels (1 row x 4 cols), keeps v in registers
// across all 64 timesteps. exc strips double-buffered in smem so each
// timestep's load serves as next timestep's "previous" (delay-1 inhibition).
// ---------------------------------------------------------------------------
#define RSTRIP     7
#define NSTRIP     10                 // ceil(65/7)
#define CG         22                 // ceil(86/4) column groups
#define K2_THREADS 160                // 22*7 = 154 active
#define BUF_ROWS   (RSTRIP + 6)       // 13
#define BUF_COLS   (W_S + 6)          // 92

__global__ void k_lgmd(const float* __restrict__ inh_w,
                       const float* __restrict__ dcmd_w,
                       float* __restrict__ out_dcmd,   // [T*B]
                       float* __restrict__ out_spk) {  // [T*B*IMG]
    const int b    = blockIdx.x;
    const int s    = blockIdx.y;
    const int row0 = s * RSTRIP;
    const int nrows = min(RSTRIP, H_S - row0);

    __shared__ float buf[2][BUF_ROWS][BUF_COLS];
    __shared__ float kw[49];
    __shared__ float red[K2_THREADS / 32];

    const int tid = threadIdx.x;
    if (tid < 49) kw[tid] = inh_w[tid];

    float* bs = &buf[0][0][0];
    for (int i = tid; i < 2 * BUF_ROWS * BUF_COLS; i += K2_THREADS) bs[i] = 0.f;

    // pixel assignment
    const int r    = tid / CG;           // row within strip
    const int cg   = tid - r * CG;
    const int row  = row0 + r;
    const int col0 = cg * 4;
    const bool active = (tid < RSTRIP * CG) && (r < nrows);
    const int ncols   = active ? min(4, W_S - col0) : 0;

    float v[4], adw[4];
    #pragma unroll
    for (int k = 0; k < 4; k++) {
        v[k]   = 0.f;
        adw[k] = (k < ncols) ? fabsf(dcmd_w[row * W_S + col0 + k]) : 0.f;
    }
    __syncthreads();

    const int loadrows  = nrows + 6;
    const int loadelems = loadrows * BUF_COLS;

    for (int t = 0; t < T_STEPS; t++) {
        float (*cur )[BUF_COLS] = buf[t & 1];
        float (*prev)[BUF_COLS] = buf[(t + 1) & 1];
        const float* excT = g_exc + ((long long)t * BATCH + b) * IMG;

        // cooperative load of current exc strip (+3 halo), zero outside
        for (int n = tid; n < loadelems; n += K2_THREADS) {
            int br = n / BUF_COLS;
            int bc = n - br * BUF_COLS;
            int gr = row0 - 3 + br;
            int gc = bc - 3;
            float val = 0.f;
            if (gr >= 0 && gr < H_S && gc >= 0 && gc < W_S)
                val = excT[gr * W_S + gc];
            cur[br][bc] = val;
        }
        __syncthreads();

        float dsum = 0.f;
        if (active) {
            // 7x7 inhibition conv on PREVIOUS exc (sliding over 4 outputs)
            float inh[4] = {0.f, 0.f, 0.f, 0.f};
            #pragma unroll
            for (int ky = 0; ky < 7; ky++) {
                float line[10];
                #pragma unroll
                for (int u = 0; u < 10; u++) line[u] = prev[r + ky][col0 + u];
                #pragma unroll
                for (int o = 0; o < 4; o++)
                    #pragma unroll
                    for (int kx = 0; kx < 7; kx++)
                        inh[o] += line[o + kx] * kw[ky * 7 + kx];
            }

            const long long obase = ((long long)t * BATCH + b) * IMG
                                    + (long long)row * W_S + col0;
            #pragma unroll
            for (int o = 0; o < 4; o++) {
                if (o < ncols) {
                    float e     = cur[r + 3][col0 + 3 + o];
                    float lg    = e + inh[o];
                    float vn    = v[o] + (lg - v[o]) * 0.5f;   // tau = 2 exact
                    float spike = (vn >= 1.0f) ? 1.0f : 0.0f;
                    out_spk[obase + o] = spike;
                    v[o]  = vn * (1.0f - spike);
                    dsum += spike * adw[o];
                }
            }
        }

        // block reduction of dcmd contribution
        #pragma unroll
        for (int off = 16; off; off >>= 1)
            dsum += __shfl_down_sync(0xffffffffu, dsum, off);
        if ((tid & 31) == 0) red[tid >> 5] = dsum;
        __syncthreads();
        if (tid == 0) {
            float tot = 0.f;
            #pragma unroll
            for (int wv = 0; wv < K2_THREADS / 32; wv++) tot += red[wv];
            atomicAdd(&out_dcmd[t * BATCH + b], tot);
        }
        __syncthreads();   // protect prev buffer before next overwrite
    }
}

__global__ void k_zero(float* p, int n) {
    int i = blockIdx.x * blockDim.x + threadIdx.x;
    if (i < n) p[i] = 0.f;
}

extern "C" void kernel_launch(void* const* d_in, const int* in_sizes, int n_in,
                              void* d_out, int out_size) {
    const float* x      = (const float*)d_in[0];
    const float* exc_w  = (const float*)d_in[1];
    const float* inh_w  = (const float*)d_in[2];
    const float* dcmd_w = (const float*)d_in[3];

    float* out      = (float*)d_out;
    float* out_dcmd = out;                         // (T,B)
    float* out_spk  = out + T_STEPS * BATCH;       // (T,B,1,H_S,W_S)

    k_zero<<<1, 1024>>>(out_dcmd, T_STEPS * BATCH);
    k_exc <<<T_STEPS * BATCH, 512>>>(x, exc_w);
    dim3 g2(BATCH, NSTRIP);
    k_lgmd<<<g2, K2_THREADS>>>(inh_w, dcmd_w, out_dcmd, out_spk);
}

// round 2
// speedup vs baseline: 1.1282x; 1.1282x over previous
#include <cuda_runtime.h>

#define HEIGHT  260
#define WIDTH   346
#define H_S     65
#define W_S     86
#define T_STEPS 64
#define BATCH   16
#define IMG     (H_S * W_S)      // 5590

// scratch: exc for all (t,b) — 64*16*5590 floats = 22.9 MB (L2-resident)
__device__ float g_exc[T_STEPS * BATCH * IMG];

// ---------------------------------------------------------------------------
// Kernel A: 4x4 avg pool (2 channels) + 2-ch 3x3 conv + ReLU, per (t,b) image
// Vectorized pooling: 1x float4 + 2x float2 per row pair -> 6 LDG per output.
// ---------------------------------------------------------------------------
__global__ void k_exc(const float* __restrict__ x, const float* __restrict__ exc_w,
                      float* __restrict__ out_dcmd) {
    const int tb = blockIdx.x;                       // t*BATCH + b
    const float* xb = x + (long long)tb * 2 * HEIGHT * WIDTH;

    __shared__ float p[2][H_S + 2][W_S + 2];         // pooled, zero-padded halo 1
    __shared__ float w[18];

    const int tid = threadIdx.x;
    if (tid < 18) w[tid] = exc_w[tid];
    if (tid == 511) out_dcmd[tb] = 0.f;              // fold k_zero into this kernel

    // zero only the halo border of p
    {
        // rows 0 and H_S+1 (each 88 wide), cols 0 and W_S+1 (each 67 tall), x2 ch
        for (int n = tid; n < 2 * (W_S + 2); n += blockDim.x) {
            int c = n / (W_S + 2), j = n % (W_S + 2);
            p[c][0][j] = 0.f;  p[c][H_S + 1][j] = 0.f;
        }
        for (int n = tid; n < 2 * (H_S + 2); n += blockDim.x) {
            int c = n / (H_S + 2), i = n % (H_S + 2);
            p[c][i][0] = 0.f;  p[c][i][W_S + 1] = 0.f;
        }
    }
    __syncthreads();

    // pooling: each task = one (c,i,j) pooled value; vector loads
    for (int n = tid; n < 2 * IMG; n += blockDim.x) {
        int c   = n / IMG;
        int rem = n - c * IMG;
        int i   = rem / W_S;
        int j   = rem - i * W_S;
        const float* src = xb + ((long long)c * HEIGHT + i * 4) * WIDTH + j * 4;
        float4 a  = *(const float4*)(src);                 // row 0 (16B aligned)
        float2 b0 = *(const float2*)(src + WIDTH);         // row 1 (8B aligned)
        float2 b1 = *(const float2*)(src + WIDTH + 2);
        float4 c4 = *(const float4*)(src + 2 * WIDTH);     // row 2 (16B aligned)
        float2 d0 = *(const float2*)(src + 3 * WIDTH);     // row 3 (8B aligned)
        float2 d1 = *(const float2*)(src + 3 * WIDTH + 2);
        float s = a.x + a.y + a.z + a.w
                + b0.x + b0.y + b1.x + b1.y
                + c4.x + c4.y + c4.z + c4.w
                + d0.x + d0.y + d1.x + d1.y;
        p[c][i + 1][j + 1] = s * (1.f / 16.f);
    }
    __syncthreads();

    // 3x3 conv over 2 channels + relu
    float* out = g_exc + (long long)tb * IMG;
    for (int n = tid; n < IMG; n += blockDim.x) {
        int i = n / W_S;
        int j = n - i * W_S;
        float acc = 0.f;
        #pragma unroll
        for (int c = 0; c < 2; c++)
            #pragma unroll
            for (int ky = 0; ky < 3; ky++)
                #pragma unroll
                for (int kx = 0; kx < 3; kx++)
                    acc += p[c][i + ky][j + kx] * w[c * 9 + ky * 3 + kx];
        out[n] = fmaxf(acc, 0.f);
    }
}

// ---------------------------------------------------------------------------
// Kernel B: recurrent LGMD dynamics. 16 batches x 9 strips of 8 rows = 144
// blocks (<=148 SMs, exactly one block per SM, no tail). 352 threads,
// 2 px/thread, v in registers across all 64 timesteps, double-buffered smem
// exc strips (current strip becomes next step's delayed inhibition input).
// ---------------------------------------------------------------------------
#define RSTRIP     8
#define NSTRIP     9                  // 9*8 = 72 >= 65
#define CG2        43                 // 86/2 column groups
#define K2_THREADS 352                // 43*8 = 344 active, 11 full warps
#define BUF_ROWS   (RSTRIP + 6)       // 14
#define BUF_COLS   (W_S + 6)          // 92

__global__ void k_lgmd(const float* __restrict__ inh_w,
                       const float* __restrict__ dcmd_w,
                       float* __restrict__ out_dcmd,   // [T*B]
                       float* __restrict__ out_spk) {  // [T*B*IMG]
    const int b     = blockIdx.x;
    const int s     = blockIdx.y;
    const int row0  = s * RSTRIP;
    const int nrows = min(RSTRIP, H_S - row0);

    __shared__ float buf[2][BUF_ROWS][BUF_COLS];
    __shared__ float kw[49];

    const int tid = threadIdx.x;
    if (tid < 49) kw[tid] = inh_w[tid];

    float* bs = &buf[0][0][0];
    for (int i = tid; i < 2 * BUF_ROWS * BUF_COLS; i += K2_THREADS) bs[i] = 0.f;

    // pixel assignment: 2 adjacent columns per thread
    const int r    = tid / CG2;          // row within strip
    const int cg   = tid - r * CG2;
    const int row  = row0 + r;
    const int col0 = cg * 2;
    const bool active = (tid < RSTRIP * CG2) && (r < nrows);

    float v0 = 0.f, v1 = 0.f;
    float adw0 = 0.f, adw1 = 0.f;
    if (active) {
        adw0 = fabsf(dcmd_w[row * W_S + col0]);
        adw1 = fabsf(dcmd_w[row * W_S + col0 + 1]);
    }
    __syncthreads();

    const int loadelems = (nrows + 6) * BUF_COLS;

    for (int t = 0; t < T_STEPS; t++) {
        float (*cur )[BUF_COLS] = buf[t & 1];
        float (*prev)[BUF_COLS] = buf[(t + 1) & 1];
        const float* excT = g_exc + ((long long)t * BATCH + b) * IMG;

        // cooperative load of current exc strip (+3 halo), zero outside
        for (int n = tid; n < loadelems; n += K2_THREADS) {
            int br = n / BUF_COLS;
            int bc = n - br * BUF_COLS;
            int gr = row0 - 3 + br;
            int gc = bc - 3;
            float val = 0.f;
            if (gr >= 0 && gr < H_S && gc >= 0 && gc < W_S)
                val = __ldg(&excT[gr * W_S + gc]);
            cur[br][bc] = val;
        }
        __syncthreads();

        float dsum = 0.f;
        if (active) {
            // 7x7 inhibition conv on PREVIOUS exc, 2 outputs per thread
            float inh0 = 0.f, inh1 = 0.f;
            #pragma unroll
            for (int ky = 0; ky < 7; ky++) {
                float line[8];
                #pragma unroll
                for (int u = 0; u < 8; u++) line[u] = prev[r + ky][col0 + u];
                #pragma unroll
                for (int kx = 0; kx < 7; kx++) {
                    float kv = kw[ky * 7 + kx];
                    inh0 += line[kx]     * kv;
                    inh1 += line[kx + 1] * kv;
                }
            }

            const long long obase = ((long long)t * BATCH + b) * IMG
                                    + (long long)row * W_S + col0;
            float e0 = cur[r + 3][col0 + 3];
            float e1 = cur[r + 3][col0 + 4];
            float vn0 = v0 + (e0 + inh0 - v0) * 0.5f;      // tau = 2 exact
            float vn1 = v1 + (e1 + inh1 - v1) * 0.5f;
            float sp0 = (vn0 >= 1.0f) ? 1.0f : 0.0f;
            float sp1 = (vn1 >= 1.0f) ? 1.0f : 0.0f;
            out_spk[obase]     = sp0;
            out_spk[obase + 1] = sp1;
            v0 = vn0 * (1.0f - sp0);
            v1 = vn1 * (1.0f - sp1);
            dsum = sp0 * adw0 + sp1 * adw1;
        }

        // warp-level reduction, one RED per warp (no smem gather, no extra bar)
        #pragma unroll
        for (int off = 16; off; off >>= 1)
            dsum += __shfl_down_sync(0xffffffffu, dsum, off);
        if ((tid & 31) == 0 && dsum != 0.f)
            atomicAdd(&out_dcmd[t * BATCH + b], dsum);

        __syncthreads();   // all reads of prev done before next load overwrites
    }
}

extern "C" void kernel_launch(void* const* d_in, const int* in_sizes, int n_in,
                              void* d_out, int out_size) {
    const float* x      = (const float*)d_in[0];
    const float* exc_w  = (const float*)d_in[1];
    const float* inh_w  = (const float*)d_in[2];
    const float* dcmd_w = (const float*)d_in[3];

    float* out      = (float*)d_out;
    float* out_dcmd = out;                         // (T,B)
    float* out_spk  = out + T_STEPS * BATCH;       // (T,B,1,H_S,W_S)

    k_exc<<<T_STEPS * BATCH, 512>>>(x, exc_w, out_dcmd);
    dim3 g2(BATCH, NSTRIP);
    k_lgmd<<<g2, K2_THREADS>>>(inh_w, dcmd_w, out_dcmd, out_spk);
}

// round 3
// speedup vs baseline: 1.3396x; 1.1874x over previous
#include <cuda_runtime.h>

#define HEIGHT  260
#define WIDTH   346
#define H_S     65
#define W_S     86
#define T_STEPS 64
#define BATCH   16
#define IMG     (H_S * W_S)      // 5590

// scratch: exc for all (t,b) — 64*16*5590 floats = 22.9 MB (L2-resident)
__device__ float g_exc[T_STEPS * BATCH * IMG];

// ---------------------------------------------------------------------------
// Kernel A: 4x4 avg pool (2 channels) + 2-ch 3x3 conv + ReLU, per (t,b) image
// DRAM-bound (737 MB input): vectorized loads, unchanged from R2.
// ---------------------------------------------------------------------------
__global__ void k_exc(const float* __restrict__ x, const float* __restrict__ exc_w,
                      float* __restrict__ out_dcmd) {
    const int tb = blockIdx.x;                       // t*BATCH + b
    const float* xb = x + (long long)tb * 2 * HEIGHT * WIDTH;

    __shared__ float p[2][H_S + 2][W_S + 2];         // pooled, zero-padded halo 1
    __shared__ float w[18];

    const int tid = threadIdx.x;
    if (tid < 18) w[tid] = exc_w[tid];
    if (tid == 511) out_dcmd[tb] = 0.f;              // fold k_zero into this kernel

    // zero only the halo border of p
    for (int n = tid; n < 2 * (W_S + 2); n += blockDim.x) {
        int c = n / (W_S + 2), j = n % (W_S + 2);
        p[c][0][j] = 0.f;  p[c][H_S + 1][j] = 0.f;
    }
    for (int n = tid; n < 2 * (H_S + 2); n += blockDim.x) {
        int c = n / (H_S + 2), i = n % (H_S + 2);
        p[c][i][0] = 0.f;  p[c][i][W_S + 1] = 0.f;
    }
    __syncthreads();

    // pooling: vector loads, 6 LDG per pooled output
    for (int n = tid; n < 2 * IMG; n += blockDim.x) {
        int c   = n / IMG;
        int rem = n - c * IMG;
        int i   = rem / W_S;
        int j   = rem - i * W_S;
        const float* src = xb + ((long long)c * HEIGHT + i * 4) * WIDTH + j * 4;
        float4 a  = *(const float4*)(src);
        float2 b0 = *(const float2*)(src + WIDTH);
        float2 b1 = *(const float2*)(src + WIDTH + 2);
        float4 c4 = *(const float4*)(src + 2 * WIDTH);
        float2 d0 = *(const float2*)(src + 3 * WIDTH);
        float2 d1 = *(const float2*)(src + 3 * WIDTH + 2);
        float s = a.x + a.y + a.z + a.w
                + b0.x + b0.y + b1.x + b1.y
                + c4.x + c4.y + c4.z + c4.w
                + d0.x + d0.y + d1.x + d1.y;
        p[c][i + 1][j + 1] = s * (1.f / 16.f);
    }
    __syncthreads();

    // 3x3 conv over 2 channels + relu
    float* out = g_exc + (long long)tb * IMG;
    for (int n = tid; n < IMG; n += blockDim.x) {
        int i = n / W_S;
        int j = n - i * W_S;
        float acc = 0.f;
        #pragma unroll
        for (int c = 0; c < 2; c++)
            #pragma unroll
            for (int ky = 0; ky < 3; ky++)
                #pragma unroll
                for (int kx = 0; kx < 3; kx++)
                    acc += p[c][i + ky][j + kx] * w[c * 9 + ky * 3 + kx];
        out[n] = fmaxf(acc, 0.f);
    }
}

// ---------------------------------------------------------------------------
// Kernel B: recurrent LGMD. 16 batches x 17 strips of 4 rows = 272 blocks of
// 352 threads -> 2 CTAs/SM. Separable 7x7 Gaussian (row pass fused with strip
// load, double-buffered so row-passed exc[t] is next step's inhibition input).
// 1 px/thread, lane = column -> conflict-free smem.
// ---------------------------------------------------------------------------
#define RS      4                  // rows per strip
#define NS      17                 // ceil(65/4)
#define BR      (RS + 6)           // 10 buffer rows
#define RAWC    (W_S + 6)          // 92
#define RBC     (W_S + 2)          // 88, padded
#define NT      352

__global__ void k_lgmd(const float* __restrict__ inh_w,
                       const float* __restrict__ dcmd_w,
                       float* __restrict__ out_dcmd,   // [T*B]
                       float* __restrict__ out_spk) {  // [T*B*IMG]
    const int b     = blockIdx.x;
    const int s     = blockIdx.y;
    const int row0  = s * RS;
    const int nrows = min(RS, H_S - row0);

    __shared__ float raw[BR][RAWC];        // raw exc strip (single-buffered)
    __shared__ float rbuf[2][BR][RBC];     // row-passed exc (double-buffered)
    __shared__ float red[NT / 32];

    const int tid = threadIdx.x;

    // separable factor: inh_w = -(u ⊗ u), u_j = -inh_w[21+j] * rsqrt(-inh_w[24])
    float u[7];
    {
        float cnorm = rsqrtf(-inh_w[3 * 7 + 3]);
        #pragma unroll
        for (int j = 0; j < 7; j++) u[j] = -inh_w[3 * 7 + j] * cnorm;
    }

    // zero both rbuf buffers (t=0 inhibition input must be 0)
    float* z = &rbuf[0][0][0];
    for (int i = tid; i < 2 * BR * RBC; i += NT) z[i] = 0.f;

    // pixel assignment: 1 px/thread, lane ~ column
    const int r = tid / W_S;
    const int c = tid - r * W_S;
    const bool active = (tid < nrows * W_S);
    const int  row = row0 + r;

    float v = 0.f;
    float adw = active ? fabsf(dcmd_w[row * W_S + c]) : 0.f;
    __syncthreads();

    for (int t = 0; t < T_STEPS; t++) {
        float (*cur )[RBC] = rbuf[t & 1];
        float (*prev)[RBC] = rbuf[(t + 1) & 1];
        const float* excT = g_exc + ((long long)t * BATCH + b) * IMG;

        // load raw exc strip (+3 halo all sides), zero outside
        #pragma unroll
        for (int n = tid; n < BR * RAWC; n += NT) {
            int br = n / RAWC;
            int bc = n - br * RAWC;
            int gr = row0 - 3 + br;
            int gc = bc - 3;
            float val = 0.f;
            if (gr >= 0 && gr < H_S && gc >= 0 && gc < W_S)
                val = __ldg(&excT[gr * W_S + gc]);
            raw[br][bc] = val;
        }
        __syncthreads();

        // row pass (horizontal 7-tap) into cur — becomes next step's prev
        for (int n = tid; n < BR * W_S; n += NT) {
            int br = n / W_S;
            int bc = n - br * W_S;
            float acc = 0.f;
            #pragma unroll
            for (int kx = 0; kx < 7; kx++) acc += raw[br][bc + kx] * u[kx];
            cur[br][bc] = acc;
        }

        // column pass on prev (delay-1 inhibition) + membrane update
        float dsum = 0.f;
        if (active) {
            float cp = 0.f;
            #pragma unroll
            for (int ky = 0; ky < 7; ky++) cp += prev[r + ky][c] * u[ky];
            float e  = raw[r + 3][c + 3];
            float vn = v + ((e - cp) - v) * 0.5f;          // tau = 2 exact
            float sp = (vn >= 1.0f) ? 1.0f : 0.0f;
            out_spk[((long long)t * BATCH + b) * IMG + (long long)row * W_S + c] = sp;
            v    = vn * (1.0f - sp);
            dsum = sp * adw;
        }

        // block reduction -> single atomic per block per step
        #pragma unroll
        for (int off = 16; off; off >>= 1)
            dsum += __shfl_down_sync(0xffffffffu, dsum, off);
        if ((tid & 31) == 0) red[tid >> 5] = dsum;
        __syncthreads();   // red visible; protects raw & cur for next iter
        if (tid == 0) {
            float tot = 0.f;
            #pragma unroll
            for (int wv = 0; wv < NT / 32; wv++) tot += red[wv];
            if (tot != 0.f) atomicAdd(&out_dcmd[t * BATCH + b], tot);
        }
    }
}

extern "C" void kernel_launch(void* const* d_in, const int* in_sizes, int n_in,
                              void* d_out, int out_size) {
    const float* x      = (const float*)d_in[0];
    const float* exc_w  = (const float*)d_in[1];
    const float* inh_w  = (const float*)d_in[2];
    const float* dcmd_w = (const float*)d_in[3];

    float* out      = (float*)d_out;
    float* out_dcmd = out;                         // (T,B)
    float* out_spk  = out + T_STEPS * BATCH;       // (T,B,1,H_S,W_S)

    k_exc<<<T_STEPS * BATCH, 512>>>(x, exc_w, out_dcmd);
    dim3 g2(BATCH, NS);
    k_lgmd<<<g2, NT>>>(inh_w, dcmd_w, out_dcmd, out_spk);
}

// round 4
// speedup vs baseline: 1.6545x; 1.2351x over previous
#include <cuda_runtime.h>

#define HEIGHT  260
#define WIDTH   346
#define H_S     65
#define W_S     86
#define T_STEPS 64
#define BATCH   16
#define IMG     (H_S * W_S)      // 5590

// scratch: exc and lgmd_in for all (t,b) — 22.9 MB each (L2-resident)
__device__ float g_exc [T_STEPS * BATCH * IMG];
__device__ float g_lgmd[T_STEPS * BATCH * IMG];

// ---------------------------------------------------------------------------
// Kernel A: 4x4 avg pool (2 ch) + 2-ch 3x3 conv + ReLU, per (t,b) image.
// DRAM-bound (733 MB input), vectorized loads.
// ---------------------------------------------------------------------------
__global__ void k_exc(const float* __restrict__ x, const float* __restrict__ exc_w,
                      float* __restrict__ out_dcmd) {
    const int tb = blockIdx.x;                       // t*BATCH + b
    const float* xb = x + (long long)tb * 2 * HEIGHT * WIDTH;

    __shared__ float p[2][H_S + 2][W_S + 2];         // pooled, zero-padded halo 1
    __shared__ float w[18];

    const int tid = threadIdx.x;
    if (tid < 18) w[tid] = exc_w[tid];
    if (tid == 511) out_dcmd[tb] = 0.f;              // zero-init dcmd output

    for (int n = tid; n < 2 * (W_S + 2); n += blockDim.x) {
        int c = n / (W_S + 2), j = n % (W_S + 2);
        p[c][0][j] = 0.f;  p[c][H_S + 1][j] = 0.f;
    }
    for (int n = tid; n < 2 * (H_S + 2); n += blockDim.x) {
        int c = n / (H_S + 2), i = n % (H_S + 2);
        p[c][i][0] = 0.f;  p[c][i][W_S + 1] = 0.f;
    }
    __syncthreads();

    for (int n = tid; n < 2 * IMG; n += blockDim.x) {
        int c   = n / IMG;
        int rem = n - c * IMG;
        int i   = rem / W_S;
        int j   = rem - i * W_S;
        const float* src = xb + ((long long)c * HEIGHT + i * 4) * WIDTH + j * 4;
        float4 a  = *(const float4*)(src);
        float2 b0 = *(const float2*)(src + WIDTH);
        float2 b1 = *(const float2*)(src + WIDTH + 2);
        float4 c4 = *(const float4*)(src + 2 * WIDTH);
        float2 d0 = *(const float2*)(src + 3 * WIDTH);
        float2 d1 = *(const float2*)(src + 3 * WIDTH + 2);
        float s = a.x + a.y + a.z + a.w
                + b0.x + b0.y + b1.x + b1.y
                + c4.x + c4.y + c4.z + c4.w
                + d0.x + d0.y + d1.x + d1.y;
        p[c][i + 1][j + 1] = s * (1.f / 16.f);
    }
    __syncthreads();

    float* out = g_exc + (long long)tb * IMG;
    for (int n = tid; n < IMG; n += blockDim.x) {
        int i = n / W_S;
        int j = n - i * W_S;
        float acc = 0.f;
        #pragma unroll
        for (int c = 0; c < 2; c++)
            #pragma unroll
            for (int ky = 0; ky < 3; ky++)
                #pragma unroll
                for (int kx = 0; kx < 3; kx++)
                    acc += p[c][i + ky][j + kx] * w[c * 9 + ky * 3 + kx];
        out[n] = fmaxf(acc, 0.f);
    }
}

// ---------------------------------------------------------------------------
// Kernel B: lgmd_in[t] = exc[t] - sepconv7x7(exc[t-1]).  FULLY PARALLEL over
// all (t,b) — the conv input is exc[t-1], not part of the v-recurrence.
// Block = (tb, row-half). Separable Gaussian: row pass then column pass.
// ---------------------------------------------------------------------------
#define HROWS  33                   // rows per half (last half has 32)
#define IH     (HROWS + 6)          // 39
#define IW     (W_S + 6)            // 92
#define IWP    (W_S + 2)            // 88 padded width for row-passed buffer

__global__ void k_inh(const float* __restrict__ inh_w) {
    const int tb   = blockIdx.x;
    const int t    = tb / BATCH;
    const int half = blockIdx.y;
    const int row0 = half * HROWS;
    const int nrows = min(HROWS, H_S - row0);
    const int tid  = threadIdx.x;

    float* out = g_lgmd + (long long)tb * IMG;
    const float* cur = g_exc + (long long)tb * IMG;

    if (t == 0) {  // inhibition buffer starts at zero: lgmd_in[0] = exc[0]
        for (int n = row0 * W_S + tid; n < (row0 + nrows) * W_S; n += blockDim.x)
            out[n] = cur[n];
        return;
    }

    __shared__ float raw[IH][IW];
    __shared__ float rp [IH][IWP];

    // separable factor: inh_w = -(u ⊗ u), u_j = -inh_w[21+j] * rsqrt(-inh_w[24])
    float u[7];
    {
        float cnorm = rsqrtf(-__ldg(&inh_w[3 * 7 + 3]));
        #pragma unroll
        for (int j = 0; j < 7; j++) u[j] = -__ldg(&inh_w[3 * 7 + j]) * cnorm;
    }

    const float* prev = g_exc + ((long long)(t - 1) * BATCH + tb % BATCH) * IMG;
    const int loadrows = nrows + 6;

    // load exc[t-1] strip with 3-halo, zero-padded
    for (int n = tid; n < loadrows * IW; n += blockDim.x) {
        int r  = n / IW;
        int c  = n - r * IW;
        int gr = row0 - 3 + r;
        int gc = c - 3;
        float val = 0.f;
        if (gr >= 0 && gr < H_S && gc >= 0 && gc < W_S)
            val = __ldg(&prev[gr * W_S + gc]);
        raw[r][c] = val;
    }
    __syncthreads();

    // horizontal 7-tap
    for (int n = tid; n < loadrows * W_S; n += blockDim.x) {
        int r = n / W_S;
        int c = n - r * W_S;
        float acc = 0.f;
        #pragma unroll
        for (int k = 0; k < 7; k++) acc += raw[r][c + k] * u[k];
        rp[r][c] = acc;
    }
    __syncthreads();

    // vertical 7-tap + subtract from exc[t]
    for (int n = tid; n < nrows * W_S; n += blockDim.x) {
        int r = n / W_S;
        int c = n - r * W_S;
        float cp = 0.f;
        #pragma unroll
        for (int k = 0; k < 7; k++) cp += rp[r + k][c] * u[k];
        int g = (row0 + r) * W_S + c;
        out[g] = __ldg(&cur[g]) - cp;
    }
}

// ---------------------------------------------------------------------------
// Kernel C: pointwise membrane scan. Thread = (b, pixel); v in a register;
// 64 coalesced streaming loads (prefetched 1 step ahead), spike store,
// block-reduced dcmd (1 atomic / block / step).
// ---------------------------------------------------------------------------
#define SC_T  256
#define SC_BX ((IMG + SC_T - 1) / SC_T)   // 22

__global__ void k_scan(const float* __restrict__ dcmd_w,
                       float* __restrict__ out_dcmd,   // [T*B]
                       float* __restrict__ out_spk) {  // [T*B*IMG]
    const int b   = blockIdx.y;
    const int px  = blockIdx.x * SC_T + threadIdx.x;
    const int tid = threadIdx.x;
    const bool active = px < IMG;

    __shared__ float red[SC_T / 32];

    const long long base = (long long)b * IMG + px;
    const float adw = active ? fabsf(__ldg(&dcmd_w[px])) : 0.f;

    float v = 0.f;
    float nxt = active ? __ldg(&g_lgmd[base]) : 0.f;

    for (int t = 0; t < T_STEPS; t++) {
        float lg = nxt;
        if (t + 1 < T_STEPS && active)
            nxt = __ldg(&g_lgmd[(long long)(t + 1) * BATCH * IMG + base]);

        float dsum = 0.f;
        if (active) {
            float vn = v + (lg - v) * 0.5f;            // tau = 2 exact
            float sp = (vn >= 1.0f) ? 1.0f : 0.0f;
            out_spk[(long long)t * BATCH * IMG + base] = sp;
            v    = vn * (1.0f - sp);
            dsum = sp * adw;
        }

        #pragma unroll
        for (int off = 16; off; off >>= 1)
            dsum += __shfl_down_sync(0xffffffffu, dsum, off);
        if ((tid & 31) == 0) red[tid >> 5] = dsum;
        __syncthreads();
        if (tid == 0) {
            float tot = 0.f;
            #pragma unroll
            for (int wv = 0; wv < SC_T / 32; wv++) tot += red[wv];
            if (tot != 0.f) atomicAdd(&out_dcmd[t * BATCH + b], tot);
        }
        __syncthreads();
    }
}

extern "C" void kernel_launch(void* const* d_in, const int* in_sizes, int n_in,
                              void* d_out, int out_size) {
    const float* x      = (const float*)d_in[0];
    const float* exc_w  = (const float*)d_in[1];
    const float* inh_w  = (const float*)d_in[2];
    const float* dcmd_w = (const float*)d_in[3];

    float* out      = (float*)d_out;
    float* out_dcmd = out;                         // (T,B)
    float* out_spk  = out + T_STEPS * BATCH;       // (T,B,1,H_S,W_S)

    k_exc<<<T_STEPS * BATCH, 512>>>(x, exc_w, out_dcmd);
    dim3 gi(T_STEPS * BATCH, 2);
    k_inh<<<gi, 512>>>(inh_w);
    dim3 gs(SC_BX, BATCH);
    k_scan<<<gs, SC_T>>>(dcmd_w, out_dcmd, out_spk);
}

// round 5
// speedup vs baseline: 1.8145x; 1.0967x over previous
#include <cuda_runtime.h>

#define HEIGHT  260
#define WIDTH   346
#define H_S     65
#define W_S     86
#define T_STEPS 64
#define BATCH   16
#define IMG     (H_S * W_S)      // 5590

// scratch (L2-resident working set ~46 MB)
__device__ float g_exc [T_STEPS * BATCH * IMG];   // exc, then overwritten with lgmd_in
__device__ float g_excr[T_STEPS * BATCH * IMG];   // row-passed (horizontal 7-tap) exc

// ---------------------------------------------------------------------------
// Kernel A: pool + 3x3 conv + ReLU  AND  horizontal 7-tap of the result.
// DRAM-bound; the h-pass rides on idle ALUs. Writes g_exc and g_excr.
// ---------------------------------------------------------------------------
__global__ void k_exc(const float* __restrict__ x, const float* __restrict__ exc_w,
                      const float* __restrict__ inh_w) {
    const int tb = blockIdx.x;                       // t*BATCH + b
    const float* xb = x + (long long)tb * 2 * HEIGHT * WIDTH;

    __shared__ float pool_[2 * 67 * 88];             // p[2][67][88], later overlaid by e[65][92]
    __shared__ float w[18];
    float (*p)[67][88] = (float(*)[67][88])pool_;

    const int tid = threadIdx.x;
    if (tid < 18) w[tid] = exc_w[tid];

    // separable factor: inh kernel = -(u ⊗ u)
    float u[7];
    {
        float cnorm = rsqrtf(-__ldg(&inh_w[3 * 7 + 3]));
        #pragma unroll
        for (int j = 0; j < 7; j++) u[j] = -__ldg(&inh_w[3 * 7 + j]) * cnorm;
    }

    // zero halo border of p
    for (int n = tid; n < 2 * 88; n += 512) {
        int c = n / 88, j = n % 88;
        p[c][0][j] = 0.f;  p[c][H_S + 1][j] = 0.f;
    }
    for (int n = tid; n < 2 * 67; n += 512) {
        int c = n / 67, i = n % 67;
        p[c][i][0] = 0.f;  p[c][i][W_S + 1] = 0.f;
    }
    __syncthreads();

    // 4x4 avg pooling, vectorized loads
    for (int n = tid; n < 2 * IMG; n += 512) {
        int c   = n / IMG;
        int rem = n - c * IMG;
        int i   = rem / W_S;
        int j   = rem - i * W_S;
        const float* src = xb + ((long long)c * HEIGHT + i * 4) * WIDTH + j * 4;
        float4 a  = *(const float4*)(src);
        float2 b0 = *(const float2*)(src + WIDTH);
        float2 b1 = *(const float2*)(src + WIDTH + 2);
        float4 c4 = *(const float4*)(src + 2 * WIDTH);
        float2 d0 = *(const float2*)(src + 3 * WIDTH);
        float2 d1 = *(const float2*)(src + 3 * WIDTH + 2);
        float s = a.x + a.y + a.z + a.w
                + b0.x + b0.y + b1.x + b1.y
                + c4.x + c4.y + c4.z + c4.w
                + d0.x + d0.y + d1.x + d1.y;
        p[c][i + 1][j + 1] = s * (1.f / 16.f);
    }
    __syncthreads();

    // 3x3 conv over 2 channels + relu -> registers
    float accl[11];
    #pragma unroll
    for (int k = 0; k < 11; k++) {
        int n = tid + k * 512;
        if (n < IMG) {
            int i = n / W_S;
            int j = n - i * W_S;
            float acc = 0.f;
            #pragma unroll
            for (int c = 0; c < 2; c++)
                #pragma unroll
                for (int ky = 0; ky < 3; ky++)
                    #pragma unroll
                    for (int kx = 0; kx < 3; kx++)
                        acc += p[c][i + ky][j + kx] * w[c * 9 + ky * 3 + kx];
            accl[k] = fmaxf(acc, 0.f);
        }
    }
    __syncthreads();                                   // all p reads done

    // overlay e[65][92] on pool_: exc with 3-col zero borders
    float (*e)[92] = (float(*)[92])pool_;
    for (int n = tid; n < H_S * 3; n += 512) {
        int i = n / 3, c = n % 3;
        e[i][c] = 0.f;  e[i][89 + c] = 0.f;
    }
    float* oexc = g_exc + (long long)tb * IMG;
    #pragma unroll
    for (int k = 0; k < 11; k++) {
        int n = tid + k * 512;
        if (n < IMG) {
            int i = n / W_S;
            int j = n - i * W_S;
            e[i][j + 3] = accl[k];
            oexc[n] = accl[k];
        }
    }
    __syncthreads();

    // horizontal 7-tap -> g_excr
    float* oexcr = g_excr + (long long)tb * IMG;
    for (int n = tid; n < IMG; n += 512) {
        int i = n / W_S;
        int j = n - i * W_S;
        float a = 0.f;
        #pragma unroll
        for (int kx = 0; kx < 7; kx++) a += e[i][j + kx] * u[kx];
        oexcr[n] = a;
    }
}

// ---------------------------------------------------------------------------
// Kernel B: vertical 7-tap of g_excr[t-1], subtracted IN PLACE from g_exc[t]
// (g_exc then holds lgmd_in). t=0 is a no-op (zero-initialized inhibition).
// ---------------------------------------------------------------------------
#define HROWS 33
__global__ void k_inh(const float* __restrict__ inh_w) {
    const int tb = blockIdx.x;
    const int t  = tb / BATCH;
    if (t == 0) return;                                // lgmd_in[0] = exc[0], in place

    const int half  = blockIdx.y;
    const int row0  = half * HROWS;
    const int nrows = min(HROWS, H_S - row0);
    const int tid   = threadIdx.x;

    __shared__ float rp[HROWS + 6][W_S];               // 39 x 86

    float u[7];
    {
        float cnorm = rsqrtf(-__ldg(&inh_w[3 * 7 + 3]));
        #pragma unroll
        for (int j = 0; j < 7; j++) u[j] = -__ldg(&inh_w[3 * 7 + j]) * cnorm;
    }

    const float* excr = g_excr + (long long)(tb - BATCH) * IMG;   // t-1, same b
    const int loadrows = nrows + 6;

    for (int n = tid; n < loadrows * W_S; n += 512) {
        int r  = n / W_S;
        int c  = n - r * W_S;
        int gr = row0 - 3 + r;
        rp[r][c] = (gr >= 0 && gr < H_S) ? __ldg(&excr[gr * W_S + c]) : 0.f;
    }
    __syncthreads();

    float* g = g_exc + (long long)tb * IMG;
    for (int n = tid; n < nrows * W_S; n += 512) {
        int r = n / W_S;
        int c = n - r * W_S;
        float cp = 0.f;
        #pragma unroll
        for (int k = 0; k < 7; k++) cp += rp[r + k][c] * u[k];
        int idx = (row0 + r) * W_S + c;
        g[idx] = g[idx] - cp;
    }
}

// ---------------------------------------------------------------------------
// Kernel C: pointwise membrane scan, barrier-free streaming, depth-4 prefetch.
// ---------------------------------------------------------------------------
#define SC_T  256
#define SC_BX ((IMG + SC_T - 1) / SC_T)   // 22

__global__ void k_scan(float* __restrict__ out_spk) {
    const int b  = blockIdx.y;
    const int px = blockIdx.x * SC_T + threadIdx.x;
    const bool act = px < IMG;

    const long long base   = (long long)b * IMG + px;
    const long long stride = (long long)BATCH * IMG;

    float v = 0.f;
    float ring[4];
    #pragma unroll
    for (int k = 0; k < 4; k++)
        ring[k] = act ? __ldg(&g_exc[k * stride + base]) : 0.f;

    #pragma unroll
    for (int t = 0; t < T_STEPS; t++) {
        float lg = ring[t & 3];
        if (t + 4 < T_STEPS)
            ring[t & 3] = act ? __ldg(&g_exc[(t + 4) * stride + base]) : 0.f;
        float vn = v + (lg - v) * 0.5f;               // tau = 2 exact
        float sp = (vn >= 1.0f) ? 1.0f : 0.0f;
        if (act) out_spk[t * stride + base] = sp;
        v = vn * (1.0f - sp);
    }
}

// ---------------------------------------------------------------------------
// Kernel D: dcmd[t,b] = sum_px spikes * |dcmd_w|. One block per (t,b),
// L2-hot float2 loads, no atomics.
// ---------------------------------------------------------------------------
__global__ void k_dcmd(const float* __restrict__ dcmd_w,
                       const float* __restrict__ spk,
                       float* __restrict__ out_dcmd) {
    const int tb  = blockIdx.x;
    const int tid = threadIdx.x;

    __shared__ float red[8];

    const float2* s  = (const float2*)(spk + (long long)tb * IMG);
    const float2* w2 = (const float2*)dcmd_w;

    float acc = 0.f;
    for (int n = tid; n < IMG / 2; n += 256) {        // IMG even: exact
        float2 sv = __ldg(&s[n]);
        float2 wv = __ldg(&w2[n]);
        acc += sv.x * fabsf(wv.x) + sv.y * fabsf(wv.y);
    }
    #pragma unroll
    for (int off = 16; off; off >>= 1)
        acc += __shfl_down_sync(0xffffffffu, acc, off);
    if ((tid & 31) == 0) red[tid >> 5] = acc;
    __syncthreads();
    if (tid == 0) {
        float tot = 0.f;
        #pragma unroll
        for (int wv = 0; wv < 8; wv++) tot += red[wv];
        out_dcmd[tb] = tot;
    }
}

extern "C" void kernel_launch(void* const* d_in, const int* in_sizes, int n_in,
                              void* d_out, int out_size) {
    const float* x      = (const float*)d_in[0];
    const float* exc_w  = (const float*)d_in[1];
    const float* inh_w  = (const float*)d_in[2];
    const float* dcmd_w = (const float*)d_in[3];

    float* out      = (float*)d_out;
    float* out_dcmd = out;                         // (T,B)
    float* out_spk  = out + T_STEPS * BATCH;       // (T,B,1,H_S,W_S)

    k_exc<<<T_STEPS * BATCH, 512>>>(x, exc_w, inh_w);
    dim3 gi(T_STEPS * BATCH, 2);
    k_inh<<<gi, 512>>>(inh_w);
    dim3 gs(SC_BX, BATCH);
    k_scan<<<gs, SC_T>>>(out_spk);
    k_dcmd<<<T_STEPS * BATCH, 256>>>(dcmd_w, out_spk, out_dcmd);
}

// round 6
// speedup vs baseline: 1.8326x; 1.0100x over previous
#include <cuda_runtime.h>

#define HEIGHT  260
#define WIDTH   346
#define H_S     65
#define W_S     86
#define T_STEPS 64
#define BATCH   16
#define IMG     (H_S * W_S)      // 5590

// scratch (L2-resident working set ~46 MB)
__device__ float g_exc [T_STEPS * BATCH * IMG];   // exc, then overwritten with lgmd_in
__device__ float g_excr[T_STEPS * BATCH * IMG];   // row-passed (horizontal 7-tap) exc

// ---------------------------------------------------------------------------
// Kernel A: pool + 3x3 conv + ReLU  AND  horizontal 7-tap of the result.
// DRAM-bound (~780 MB); the h-pass rides on idle ALUs.
// ---------------------------------------------------------------------------
__global__ void k_exc(const float* __restrict__ x, const float* __restrict__ exc_w,
                      const float* __restrict__ inh_w, float* __restrict__ out_dcmd) {
    const int tb = blockIdx.x;                       // t*BATCH + b
    const float* xb = x + (long long)tb * 2 * HEIGHT * WIDTH;

    __shared__ float pool_[2 * 67 * 88];             // p[2][67][88], later overlaid by e[65][92]
    __shared__ float w[18];
    float (*p)[67][88] = (float(*)[67][88])pool_;

    const int tid = threadIdx.x;
    if (tid < 18) w[tid] = exc_w[tid];
    if (tid == 511) out_dcmd[tb] = 0.f;              // zero-init dcmd (poisoned by harness)

    float u[7];
    {
        float cnorm = rsqrtf(-__ldg(&inh_w[3 * 7 + 3]));
        #pragma unroll
        for (int j = 0; j < 7; j++) u[j] = -__ldg(&inh_w[3 * 7 + j]) * cnorm;
    }

    for (int n = tid; n < 2 * 88; n += 512) {
        int c = n / 88, j = n % 88;
        p[c][0][j] = 0.f;  p[c][H_S + 1][j] = 0.f;
    }
    for (int n = tid; n < 2 * 67; n += 512) {
        int c = n / 67, i = n % 67;
        p[c][i][0] = 0.f;  p[c][i][W_S + 1] = 0.f;
    }
    __syncthreads();

    // 4x4 avg pooling, vectorized loads
    for (int n = tid; n < 2 * IMG; n += 512) {
        int c   = n / IMG;
        int rem = n - c * IMG;
        int i   = rem / W_S;
        int j   = rem - i * W_S;
        const float* src = xb + ((long long)c * HEIGHT + i * 4) * WIDTH + j * 4;
        float4 a  = *(const float4*)(src);
        float2 b0 = *(const float2*)(src + WIDTH);
        float2 b1 = *(const float2*)(src + WIDTH + 2);
        float4 c4 = *(const float4*)(src + 2 * WIDTH);
        float2 d0 = *(const float2*)(src + 3 * WIDTH);
        float2 d1 = *(const float2*)(src + 3 * WIDTH + 2);
        float s = a.x + a.y + a.z + a.w
                + b0.x + b0.y + b1.x + b1.y
                + c4.x + c4.y + c4.z + c4.w
                + d0.x + d0.y + d1.x + d1.y;
        p[c][i + 1][j + 1] = s * (1.f / 16.f);
    }
    __syncthreads();

    // 3x3 conv over 2 channels + relu -> registers
    float accl[11];
    #pragma unroll
    for (int k = 0; k < 11; k++) {
        int n = tid + k * 512;
        if (n < IMG) {
            int i = n / W_S;
            int j = n - i * W_S;
            float acc = 0.f;
            #pragma unroll
            for (int c = 0; c < 2; c++)
                #pragma unroll
                for (int ky = 0; ky < 3; ky++)
                    #pragma unroll
                    for (int kx = 0; kx < 3; kx++)
                        acc += p[c][i + ky][j + kx] * w[c * 9 + ky * 3 + kx];
            accl[k] = fmaxf(acc, 0.f);
        }
    }
    __syncthreads();

    // overlay e[65][92]: exc with 3-col zero borders
    float (*e)[92] = (float(*)[92])pool_;
    for (int n = tid; n < H_S * 3; n += 512) {
        int i = n / 3, c = n % 3;
        e[i][c] = 0.f;  e[i][89 + c] = 0.f;
    }
    float* oexc = g_exc + (long long)tb * IMG;
    #pragma unroll
    for (int k = 0; k < 11; k++) {
        int n = tid + k * 512;
        if (n < IMG) {
            int i = n / W_S;
            int j = n - i * W_S;
            e[i][j + 3] = accl[k];
            oexc[n] = accl[k];
        }
    }
    __syncthreads();

    // horizontal 7-tap -> g_excr
    float* oexcr = g_excr + (long long)tb * IMG;
    for (int n = tid; n < IMG; n += 512) {
        int i = n / W_S;
        int j = n - i * W_S;
        float a = 0.f;
        #pragma unroll
        for (int kx = 0; kx < 7; kx++) a += e[i][j + kx] * u[kx];
        oexcr[n] = a;
    }
}

// ---------------------------------------------------------------------------
// Kernel B: vertical 7-tap of g_excr[t-1], subtracted IN PLACE from g_exc[t].
// float2 throughout (W_S = 86 -> 43 float2 per row). t=0 is a no-op.
// ---------------------------------------------------------------------------
#define HROWS 33
#define W2    43
__global__ void k_inh(const float* __restrict__ inh_w) {
    const int tb = blockIdx.x;
    const int t  = tb / BATCH;
    if (t == 0) return;

    const int half  = blockIdx.y;
    const int row0  = half * HROWS;
    const int nrows = min(HROWS, H_S - row0);
    const int tid   = threadIdx.x;

    __shared__ float2 rp[HROWS + 6][W2];               // 39 x 43 float2

    float u[7];
    {
        float cnorm = rsqrtf(-__ldg(&inh_w[3 * 7 + 3]));
        #pragma unroll
        for (int j = 0; j < 7; j++) u[j] = -__ldg(&inh_w[3 * 7 + j]) * cnorm;
    }

    const float2* excr = (const float2*)(g_excr + (long long)(tb - BATCH) * IMG);
    const int loadrows = nrows + 6;

    for (int n = tid; n < loadrows * W2; n += 512) {
        int r  = n / W2;
        int c  = n - r * W2;
        int gr = row0 - 3 + r;
        rp[r][c] = (gr >= 0 && gr < H_S) ? __ldg(&excr[gr * W2 + c])
                                         : make_float2(0.f, 0.f);
    }
    __syncthreads();

    float2* g = (float2*)(g_exc + (long long)tb * IMG);
    for (int n = tid; n < nrows * W2; n += 512) {
        int r = n / W2;
        int c = n - r * W2;
        float cx = 0.f, cy = 0.f;
        #pragma unroll
        for (int k = 0; k < 7; k++) {
            float2 rv = rp[r + k][c];
            cx += rv.x * u[k];
            cy += rv.y * u[k];
        }
        int idx = (row0 + r) * W2 + c;
        float2 gv = g[idx];
        gv.x -= cx;  gv.y -= cy;
        g[idx] = gv;
    }
}

// ---------------------------------------------------------------------------
// Kernel C: pointwise membrane scan + FUSED dcmd reduction.
// 2 px/thread (float2), depth-4 prefetch ring, barrier-free: per-step
// warp-shfl reduce + one RED per warp. 22x16 = 352 blocks of 128 threads.
// ---------------------------------------------------------------------------
#define SCT   128
#define IMG2  (IMG / 2)                    // 2795
#define SCB   ((IMG2 + SCT - 1) / SCT)     // 22

__global__ void k_scan(const float* __restrict__ dcmd_w,
                       float* __restrict__ out_dcmd,
                       float* __restrict__ out_spk) {
    const int b   = blockIdx.y;
    const int tid = threadIdx.x;
    const int p2  = blockIdx.x * SCT + tid;
    const bool act = p2 < IMG2;

    const long long base2   = (long long)b * IMG2 + p2;
    const long long stride2 = (long long)BATCH * IMG2;
    const float2* lg2 = (const float2*)g_exc;
    float2* out2 = (float2*)out_spk;

    float a0 = 0.f, a1 = 0.f;
    if (act) {
        float2 wv = __ldg(&((const float2*)dcmd_w)[p2]);
        a0 = fabsf(wv.x);  a1 = fabsf(wv.y);
    }

    float v0 = 0.f, v1 = 0.f;
    float2 ring[4];
    #pragma unroll
    for (int k = 0; k < 4; k++)
        ring[k] = act ? __ldg(&lg2[k * stride2 + base2]) : make_float2(0.f, 0.f);

    #pragma unroll
    for (int t = 0; t < T_STEPS; t++) {
        float2 lg = ring[t & 3];
        if (t + 4 < T_STEPS)
            ring[t & 3] = act ? __ldg(&lg2[(t + 4) * stride2 + base2])
                              : make_float2(0.f, 0.f);

        float vn0 = v0 + (lg.x - v0) * 0.5f;           // tau = 2 exact
        float vn1 = v1 + (lg.y - v1) * 0.5f;
        float sp0 = (vn0 >= 1.0f) ? 1.0f : 0.0f;
        float sp1 = (vn1 >= 1.0f) ? 1.0f : 0.0f;
        if (act) out2[t * stride2 + base2] = make_float2(sp0, sp1);
        v0 = vn0 * (1.0f - sp0);
        v1 = vn1 * (1.0f - sp1);

        float dsum = sp0 * a0 + sp1 * a1;
        #pragma unroll
        for (int off = 16; off; off >>= 1)
            dsum += __shfl_down_sync(0xffffffffu, dsum, off);
        if ((tid & 31) == 0 && dsum != 0.f)
            atomicAdd(&out_dcmd[t * BATCH + b], dsum);   // RED, result unused
    }
}

extern "C" void kernel_launch(void* const* d_in, const int* in_sizes, int n_in,
                              void* d_out, int out_size) {
    const float* x      = (const float*)d_in[0];
    const float* exc_w  = (const float*)d_in[1];
    const float* inh_w  = (const float*)d_in[2];
    const float* dcmd_w = (const float*)d_in[3];

    float* out      = (float*)d_out;
    float* out_dcmd = out;                         // (T,B)
    float* out_spk  = out + T_STEPS * BATCH;       // (T,B,1,H_S,W_S)

    k_exc<<<T_STEPS * BATCH, 512>>>(x, exc_w, inh_w, out_dcmd);
    dim3 gi(T_STEPS * BATCH, 2);
    k_inh<<<gi, 512>>>(inh_w);
    dim3 gs(SCB, BATCH);
    k_scan<<<gs, SCT>>>(dcmd_w, out_dcmd, out_spk);
}